// round 10
// baseline (speedup 1.0000x reference)
#include <cuda_runtime.h>
#include <cuda_bf16.h>
#include <math.h>
#include <stdint.h>

#define B_  8
#define N_  2048
#define C_  1024
#define H_  16
#define D_  64
#define M_  (B_*N_)   // 16384
#define LN10000 9.210340371976184f
#define NKPART 8

// ---------------- device scratch (allocation-free contract) ----------------
__device__ float g_q[M_*C_];                 // gelu(q)+0.21, PRE-rope
__device__ float g_k[M_*C_];                 // gelu(k)+0.21, PRE-rope
__device__ float g_v[M_*C_];
__device__ float g_attn[M_*C_];
__device__ float g_ksum[B_*C_];
__device__ float g_kv[B_*H_*D_*D_];
__device__ float g_kvp[NKPART][B_*H_*D_*D_];
__device__ float g_ksump[NKPART][B_*C_];
__device__ float2 g_tab[N_*(C_/2)];          // rope (cos,sin) per (n, pair)
__device__ __nv_bfloat16 g_xhi[M_*C_];
__device__ __nv_bfloat16 g_xlo[M_*C_];
__device__ __nv_bfloat16 g_whi[3][C_*C_];
__device__ __nv_bfloat16 g_wlo[3][C_*C_];

__device__ __forceinline__ float gelu_exact(float x){
    return 0.5f*x*(1.0f+erff(x*0.70710678118654752f));
}
__device__ __forceinline__ uint32_t smem_u32(const void* p){
    uint32_t a;
    asm("{ .reg .u64 t; cvta.to.shared.u64 t, %1; cvt.u32.u64 %0, t; }" : "=r"(a) : "l"(p));
    return a;
}
__device__ __forceinline__ void ldm4(uint32_t* r, uint32_t addr){
    asm volatile("ldmatrix.sync.aligned.m8n8.x4.shared.b16 {%0,%1,%2,%3}, [%4];"
        : "=r"(r[0]),"=r"(r[1]),"=r"(r[2]),"=r"(r[3]) : "r"(addr));
}
__device__ __forceinline__ void mma16816(float* c, const uint32_t* a, const uint32_t* b){
    asm volatile("mma.sync.aligned.m16n8k16.row.col.f32.bf16.bf16.f32 "
        "{%0,%1,%2,%3}, {%4,%5,%6,%7}, {%8,%9}, {%0,%1,%2,%3};"
        : "+f"(c[0]), "+f"(c[1]), "+f"(c[2]), "+f"(c[3])
        : "r"(a[0]), "r"(a[1]), "r"(a[2]), "r"(a[3]), "r"(b[0]), "r"(b[1]));
}

// ---------------- rope table ----------------
__global__ void rope_table_kernel(){
    int idx = blockIdx.x*256 + threadIdx.x;      // n*512 + p
    int n = idx >> 9;
    int p = idx & 511;
    float invf = expf(-((float)(2*p) / 1024.f) * LN10000);
    float s, c;
    sincosf((float)n * invf, &s, &c);
    g_tab[idx] = make_float2(c, s);
}

// ---------------- fp32 -> bf16 hi/lo split ----------------
__global__ void conv_x_kernel(const float* __restrict__ X){
    size_t i = ((size_t)blockIdx.x*256 + threadIdx.x)*4;
    float4 v = *(const float4*)(X + i);
    __nv_bfloat16 h0 = __float2bfloat16(v.x), h1 = __float2bfloat16(v.y);
    __nv_bfloat16 h2 = __float2bfloat16(v.z), h3 = __float2bfloat16(v.w);
    __nv_bfloat16 l0 = __float2bfloat16(v.x - __bfloat162float(h0));
    __nv_bfloat16 l1 = __float2bfloat16(v.y - __bfloat162float(h1));
    __nv_bfloat16 l2 = __float2bfloat16(v.z - __bfloat162float(h2));
    __nv_bfloat16 l3 = __float2bfloat16(v.w - __bfloat162float(h3));
    __nv_bfloat162 ha = __halves2bfloat162(h0,h1), hb = __halves2bfloat162(h2,h3);
    __nv_bfloat162 la = __halves2bfloat162(l0,l1), lb = __halves2bfloat162(l2,l3);
    uint2 hu, lu;
    hu.x = *(uint32_t*)&ha; hu.y = *(uint32_t*)&hb;
    lu.x = *(uint32_t*)&la; lu.y = *(uint32_t*)&lb;
    *(uint2*)(g_xhi + i) = hu;
    *(uint2*)(g_xlo + i) = lu;
}

__global__ void conv_w_kernel(const float* __restrict__ Wq,
                              const float* __restrict__ Wk,
                              const float* __restrict__ Wv){
    const int w = blockIdx.y;
    const float* W = (w==0)? Wq : (w==1)? Wk : Wv;
    size_t i = ((size_t)blockIdx.x*256 + threadIdx.x)*4;
    float4 v = *(const float4*)(W + i);
    __nv_bfloat16 h0 = __float2bfloat16(v.x), h1 = __float2bfloat16(v.y);
    __nv_bfloat16 h2 = __float2bfloat16(v.z), h3 = __float2bfloat16(v.w);
    __nv_bfloat16 l0 = __float2bfloat16(v.x - __bfloat162float(h0));
    __nv_bfloat16 l1 = __float2bfloat16(v.y - __bfloat162float(h1));
    __nv_bfloat16 l2 = __float2bfloat16(v.z - __bfloat162float(h2));
    __nv_bfloat16 l3 = __float2bfloat16(v.w - __bfloat162float(h3));
    __nv_bfloat162 ha = __halves2bfloat162(h0,h1), hb = __halves2bfloat162(h2,h3);
    __nv_bfloat162 la = __halves2bfloat162(l0,l1), lb = __halves2bfloat162(l2,l3);
    uint2 hu, lu;
    hu.x = *(uint32_t*)&ha; hu.y = *(uint32_t*)&hb;
    lu.x = *(uint32_t*)&la; lu.y = *(uint32_t*)&lb;
    *(uint2*)(g_whi[w] + i) = hu;
    *(uint2*)(g_wlo[w] + i) = lu;
}

// ---------------------------------------------------------------------------
// mma.sync bf16 GEMM, concat-K = [xhi|xhi|xlo] . [whi|wlo|whi]
// CTA tile 128x256x64, 4-stage cp.async (prefetch dist 3),
// 8 warps as 2m x 4n, warp tile 64x64 (ratio: 32 MMA per 8 ldmatrix).
// ---------------------------------------------------------------------------
#define BM 128
#define BN 256
#define BK 64
#define ASTRIDE 144                     // 128B row + 16B pad
#define A_TILE (BM*ASTRIDE)             // 18432
#define B_TILE (BN*ASTRIDE)             // 36864
#define STAGE_BYTES (A_TILE + B_TILE)   // 55296
#define NSTAGE 4
#define SMEM_TOT (NSTAGE*STAGE_BYTES)   // 221184
#define NCHUNK 48

__device__ __forceinline__ void stage_load(uint32_t sa, uint32_t sbB, int chunk,
                                           int w, int m0, int n0, int tid){
    const int pass = chunk >> 4;
    const int kk = (chunk & 15) << 6;   // bf16 element offset in [0,1024)
    const __nv_bfloat16* Asrc = (pass < 2) ? g_xhi : g_xlo;
    const __nv_bfloat16* Bsrc = (pass == 1) ? g_wlo[w] : g_whi[w];
    #pragma unroll
    for (int r = 0; r < 4; r++){
        int cid = tid + r*256;          // 0..1023
        int row = cid >> 3, ch = cid & 7;
        uint64_t ga = (uint64_t)__cvta_generic_to_global(
            (const void*)(Asrc + (size_t)(m0+row)*C_ + kk + ch*8));
        asm volatile("cp.async.cg.shared.global [%0], [%1], 16;"
                     :: "r"(sa + row*ASTRIDE + ch*16), "l"(ga));
    }
    #pragma unroll
    for (int r = 0; r < 8; r++){
        int cid = tid + r*256;          // 0..2047
        int row = cid >> 3, ch = cid & 7;
        uint64_t gb = (uint64_t)__cvta_generic_to_global(
            (const void*)(Bsrc + (size_t)(n0+row)*C_ + kk + ch*8));
        asm volatile("cp.async.cg.shared.global [%0], [%1], 16;"
                     :: "r"(sbB + row*ASTRIDE + ch*16), "l"(gb));
    }
}

__global__ void __launch_bounds__(256) mma_gemm_kernel(
    const float* __restrict__ bq, const float* __restrict__ bk, const float* __restrict__ bv)
{
    extern __shared__ char smem[];
    const int tid  = threadIdx.x;
    const int lane = tid & 31;
    const int wid  = tid >> 5;
    const int wm   = wid & 1;       // m offset *64
    const int wn   = wid >> 1;      // n offset *64
    const int w  = blockIdx.z;
    const int n0 = blockIdx.x * BN;
    const int m0 = blockIdx.y * BM;
    const uint32_t sb = smem_u32(smem);

    float acc[4][8][4];
    #pragma unroll
    for (int a = 0; a < 4; a++)
        #pragma unroll
        for (int bb = 0; bb < 8; bb++)
            #pragma unroll
            for (int cdx = 0; cdx < 4; cdx++) acc[a][bb][cdx] = 0.f;

    // prologue: stages 0..2
    #pragma unroll
    for (int s = 0; s < 3; s++){
        stage_load(sb + s*STAGE_BYTES, sb + s*STAGE_BYTES + A_TILE, s, w, m0, n0, tid);
        asm volatile("cp.async.commit_group;" ::: "memory");
    }

    const uint32_t a_off = (uint32_t)((wm*64 + (lane & 15))*ASTRIDE + ((lane >> 4) << 3)*2);
    const uint32_t b_off = (uint32_t)((wn*64 + (lane & 7) + ((lane >> 4) << 3))*ASTRIDE
                                      + (((lane >> 3) & 1) << 3)*2);

    int bufc = 0;
    for (int i = 0; i < NCHUNK; i++){
        if (i < NCHUNK-2)        asm volatile("cp.async.wait_group 2;" ::: "memory");
        else if (i == NCHUNK-2)  asm volatile("cp.async.wait_group 1;" ::: "memory");
        else                     asm volatile("cp.async.wait_group 0;" ::: "memory");
        __syncthreads();

        if (i + 3 < NCHUNK){
            int bn = bufc + 3; if (bn >= NSTAGE) bn -= NSTAGE;
            stage_load(sb + bn*STAGE_BYTES, sb + bn*STAGE_BYTES + A_TILE,
                       i+3, w, m0, n0, tid);
            asm volatile("cp.async.commit_group;" ::: "memory");
        }

        const uint32_t abase = sb + bufc*STAGE_BYTES;
        const uint32_t bbase = abase + A_TILE;
        #pragma unroll
        for (int ks = 0; ks < 4; ks++){
            uint32_t af[4][4];
            #pragma unroll
            for (int fm = 0; fm < 4; fm++)
                ldm4(af[fm], abase + a_off + fm*16*ASTRIDE + ks*32);
            #pragma unroll
            for (int fn2 = 0; fn2 < 4; fn2++){
                uint32_t bf[4];
                ldm4(bf, bbase + b_off + fn2*16*ASTRIDE + ks*32);
                #pragma unroll
                for (int fm = 0; fm < 4; fm++){
                    mma16816(acc[fm][fn2*2],   af[fm], bf);
                    mma16816(acc[fm][fn2*2+1], af[fm], bf+2);
                }
            }
        }
        if (++bufc == NSTAGE) bufc = 0;
    }

    // epilogue: bias + (gelu+0.21 for q,k)
    const float* bias = (w==0)? bq : (w==1)? bk : bv;
    float* OUT = (w==0)? g_q : (w==1)? g_k : g_v;
    #pragma unroll
    for (int fm = 0; fm < 4; fm++){
        const int row0 = m0 + wm*64 + fm*16 + (lane >> 2);
        #pragma unroll
        for (int fn = 0; fn < 8; fn++){
            const int col = n0 + wn*64 + fn*8 + (lane & 3)*2;
            const float b0 = bias[col], b1 = bias[col+1];
            float v0 = acc[fm][fn][0] + b0;
            float v1 = acc[fm][fn][1] + b1;
            float v2 = acc[fm][fn][2] + b0;
            float v3 = acc[fm][fn][3] + b1;
            if (w < 2){
                v0 = gelu_exact(v0) + 0.21f;
                v1 = gelu_exact(v1) + 0.21f;
                v2 = gelu_exact(v2) + 0.21f;
                v3 = gelu_exact(v3) + 0.21f;
            }
            float2 o01; o01.x = v0; o01.y = v1;
            float2 o23; o23.x = v2; o23.y = v3;
            *(float2*)(OUT + (size_t)row0*C_ + col)     = o01;
            *(float2*)(OUT + (size_t)(row0+8)*C_ + col) = o23;
        }
    }
}

// ---------------------------------------------------------------------------
// kv partials: part p covers rows [p*256, p*256+256).
// ---------------------------------------------------------------------------
__global__ __launch_bounds__(256,1) void kv_part_kernel()
{
    const int bh = blockIdx.x;
    const int part = blockIdx.y;
    const int b = bh >> 4, h = bh & 15;
    __shared__ float ks[64][68];
    __shared__ float vs[64][68];
    __shared__ float cs[16][68];

    const int tid = threadIdx.x;
    const int te = tid & 15, td = tid >> 4;
    const int c4 = tid & 15;
    const int p0 = (h*D_ + c4*4) >> 1;

    float acc[4][4];
    #pragma unroll
    for (int i = 0; i < 4; i++)
        #pragma unroll
        for (int j = 0; j < 4; j++) acc[i][j] = 0.f;
    float csum[4] = {0.f,0.f,0.f,0.f};

    const float* kbase = g_k + (size_t)b*N_*C_ + h*D_;
    const float* vbase = g_v + (size_t)b*N_*C_ + h*D_;
    const int nstart = part * (N_/NKPART);

    for (int nt = nstart; nt < nstart + N_/NKPART; nt += 64) {
        #pragma unroll
        for (int l = 0; l < 4; l++) {
            int row = (tid >> 4) + l*16;
            int n = nt + row;
            float4 kk = *(const float4*)(kbase + (size_t)n*C_ + c4*4);
            csum[0] += kk.x; csum[1] += kk.y; csum[2] += kk.z; csum[3] += kk.w;
            float2 t0 = g_tab[n*(C_/2) + p0];
            float2 t1 = g_tab[n*(C_/2) + p0 + 1];
            float4 r;
            r.x = kk.x*t0.x - kk.y*t0.y;
            r.y = kk.y*t0.x + kk.x*t0.y;
            r.z = kk.z*t1.x - kk.w*t1.y;
            r.w = kk.w*t1.x + kk.z*t1.y;
            *(float4*)&ks[row][c4*4] = r;
            *(float4*)&vs[row][c4*4] = *(const float4*)(vbase + (size_t)n*C_ + c4*4);
        }
        __syncthreads();
        #pragma unroll 8
        for (int nn = 0; nn < 64; nn++) {
            float4 kd = *(const float4*)&ks[nn][td*4];
            float4 ve = *(const float4*)&vs[nn][te*4];
            float kv4[4] = {kd.x, kd.y, kd.z, kd.w};
            float vv4[4] = {ve.x, ve.y, ve.z, ve.w};
            #pragma unroll
            for (int i = 0; i < 4; i++)
                #pragma unroll
                for (int j = 0; j < 4; j++)
                    acc[i][j] = fmaf(kv4[i], vv4[j], acc[i][j]);
        }
        __syncthreads();
    }

    *(float4*)&cs[tid>>4][c4*4] = make_float4(csum[0], csum[1], csum[2], csum[3]);
    __syncthreads();
    if (tid < 64) {
        float s = 0.f;
        #pragma unroll
        for (int r2 = 0; r2 < 16; r2++) s += cs[r2][tid];
        g_ksump[part][b*C_ + h*D_ + tid] = s;
    }

    float* kvout = g_kvp[part] + ((size_t)bh*D_ + td*4)*D_ + te*4;
    #pragma unroll
    for (int i = 0; i < 4; i++) {
        float4 o;
        o.x = acc[i][0]; o.y = acc[i][1]; o.z = acc[i][2]; o.w = acc[i][3];
        *(float4*)(kvout + i*D_) = o;
    }
}

__global__ __launch_bounds__(256,1) void kv_reduce_kernel()
{
    const int idx = blockIdx.x*256 + threadIdx.x;   // 0 .. B*H*D*D-1
    float s = 0.f;
    #pragma unroll
    for (int p = 0; p < NKPART; p++) s += g_kvp[p][idx];
    g_kv[idx] = s * (1.f / (float)N_);
    if (idx < B_*C_) {
        float t = 0.f;
        #pragma unroll
        for (int p = 0; p < NKPART; p++) t += g_ksump[p][idx];
        g_ksum[idx] = t;
    }
}

// ---------------------------------------------------------------------------
// out_attn = z * (rope(q) @ kv); z = 1/(dot(q_pre, kmean)+1e-6). Table rope.
// ---------------------------------------------------------------------------
__global__ __launch_bounds__(256,1) void zout_kernel()
{
    const int bh = blockIdx.y;
    const int b = bh >> 4, h = bh & 15;
    const int n0 = blockIdx.x * 64;

    __shared__ float qs[64][68];
    __shared__ float kvs[64][68];
    __shared__ float kms[64];
    __shared__ float zsh[64];

    const int tid = threadIdx.x;
    const int row = tid >> 2;
    const int qtr = tid & 3;

    if (tid < 64) kms[tid] = g_ksum[b*C_ + h*D_ + tid] * (1.f / (float)N_);
    __syncthreads();

    const int n = n0 + row;
    const float* qrow = g_q + ((size_t)(b*N_ + n))*C_ + h*D_;
    const int pbase = (h*D_ + qtr*16) >> 1;
    float zp = 0.f;
    #pragma unroll
    for (int l = 0; l < 4; l++) {
        int cl = qtr*16 + l*4;
        float4 qv = *(const float4*)(qrow + cl);
        zp += qv.x*kms[cl] + qv.y*kms[cl+1] + qv.z*kms[cl+2] + qv.w*kms[cl+3];
        float2 t0 = g_tab[n*(C_/2) + pbase + l*2];
        float2 t1 = g_tab[n*(C_/2) + pbase + l*2 + 1];
        float4 r;
        r.x = qv.x*t0.x - qv.y*t0.y;
        r.y = qv.y*t0.x + qv.x*t0.y;
        r.z = qv.z*t1.x - qv.w*t1.y;
        r.w = qv.w*t1.x + qv.z*t1.y;
        *(float4*)&qs[row][cl] = r;
    }
    #pragma unroll
    for (int l = 0; l < 4; l++) {
        int idx = tid + l*256;
        int rd = idx >> 4;
        int cc4 = idx & 15;
        *(float4*)&kvs[rd][cc4*4] = *(const float4*)(g_kv + (size_t)bh*D_*D_ + rd*D_ + cc4*4);
    }
    zp += __shfl_xor_sync(0xffffffffu, zp, 1);
    zp += __shfl_xor_sync(0xffffffffu, zp, 2);
    if (qtr == 0) zsh[row] = 1.f / (zp + 1e-6f);
    __syncthreads();

    float acc[16];
    #pragma unroll
    for (int e = 0; e < 16; e++) acc[e] = 0.f;
    #pragma unroll 8
    for (int d = 0; d < 64; d++) {
        float qv = qs[row][d];
        #pragma unroll
        for (int l = 0; l < 4; l++) {
            float4 k4 = *(const float4*)&kvs[d][qtr*16 + l*4];
            acc[l*4+0] = fmaf(qv, k4.x, acc[l*4+0]);
            acc[l*4+1] = fmaf(qv, k4.y, acc[l*4+1]);
            acc[l*4+2] = fmaf(qv, k4.z, acc[l*4+2]);
            acc[l*4+3] = fmaf(qv, k4.w, acc[l*4+3]);
        }
    }
    const float z = zsh[row];
    float* o = g_attn + ((size_t)(b*N_ + n))*C_ + h*D_ + qtr*16;
    #pragma unroll
    for (int l = 0; l < 4; l++) {
        float4 r;
        r.x = acc[l*4+0]*z; r.y = acc[l*4+1]*z; r.z = acc[l*4+2]*z; r.w = acc[l*4+3]*z;
        *(float4*)(o + l*4) = r;
    }
}

// ---------------------------------------------------------------------------
// residual + LayerNorm
// ---------------------------------------------------------------------------
__global__ __launch_bounds__(256,1) void ln_kernel(
    const float* __restrict__ X,
    const float* __restrict__ gamma,
    const float* __restrict__ beta,
    float* __restrict__ out)
{
    const int m = blockIdx.x;
    const int tid = threadIdx.x;
    const float* xr = X + (size_t)m*C_;
    const float* ar = g_attn + (size_t)m*C_;

    float4 xv = *(const float4*)(xr + tid*4);
    float4 av = *(const float4*)(ar + tid*4);
    float4 r;
    r.x = xv.x + av.x; r.y = xv.y + av.y; r.z = xv.z + av.z; r.w = xv.w + av.w;

    float s1 = r.x + r.y + r.z + r.w;
    float s2 = r.x*r.x + r.y*r.y + r.z*r.z + r.w*r.w;
    #pragma unroll
    for (int o = 16; o > 0; o >>= 1) {
        s1 += __shfl_xor_sync(0xffffffffu, s1, o);
        s2 += __shfl_xor_sync(0xffffffffu, s2, o);
    }
    __shared__ float rs1[8], rs2[8], stats[2];
    int wid = tid >> 5, lane = tid & 31;
    if (lane == 0) { rs1[wid] = s1; rs2[wid] = s2; }
    __syncthreads();
    if (tid == 0) {
        float a = 0.f, bsum = 0.f;
        #pragma unroll
        for (int i = 0; i < 8; i++) { a += rs1[i]; bsum += rs2[i]; }
        stats[0] = a; stats[1] = bsum;
    }
    __syncthreads();
    float mean = stats[0] * (1.f / (float)C_);
    float var  = stats[1] * (1.f / (float)C_) - mean*mean;
    float inv  = rsqrtf(var + 1e-12f);

    float4 g4 = *(const float4*)(gamma + tid*4);
    float4 b4 = *(const float4*)(beta + tid*4);
    float4 o;
    o.x = (r.x - mean)*inv*g4.x + b4.x;
    o.y = (r.y - mean)*inv*g4.y + b4.y;
    o.z = (r.z - mean)*inv*g4.z + b4.z;
    o.w = (r.w - mean)*inv*g4.w + b4.w;
    *(float4*)(out + (size_t)m*C_ + tid*4) = o;
}

extern "C" void kernel_launch(void* const* d_in, const int* in_sizes, int n_in,
                              void* d_out, int out_size)
{
    const float* x     = (const float*)d_in[0];
    const float* Wq    = (const float*)d_in[1];
    const float* bq    = (const float*)d_in[2];
    const float* Wk    = (const float*)d_in[3];
    const float* bk    = (const float*)d_in[4];
    const float* Wv    = (const float*)d_in[5];
    const float* bv    = (const float*)d_in[6];
    const float* gamma = (const float*)d_in[7];
    const float* beta  = (const float*)d_in[8];
    float* out = (float*)d_out;

    cudaFuncSetAttribute(mma_gemm_kernel, cudaFuncAttributeMaxDynamicSharedMemorySize, SMEM_TOT);

    rope_table_kernel<<<(N_*(C_/2))/256, 256>>>();
    conv_x_kernel<<<(M_*C_)/1024, 256>>>(x);
    conv_w_kernel<<<dim3((C_*C_)/1024, 3), 256>>>(Wq, Wk, Wv);
    mma_gemm_kernel<<<dim3(C_/BN, M_/BM, 3), 256, SMEM_TOT>>>(bq, bk, bv);
    kv_part_kernel<<<dim3(B_*H_, NKPART), 256>>>();
    kv_reduce_kernel<<<(B_*H_*D_*D_)/256, 256>>>();
    zout_kernel<<<dim3(N_/64, B_*H_), 256>>>();
    ln_kernel<<<M_, 256>>>(x, gamma, beta, out);
}

// round 13
// speedup vs baseline: 1.3858x; 1.3858x over previous
#include <cuda_runtime.h>
#include <cuda_fp16.h>
#include <math.h>
#include <stdint.h>

#define B_  8
#define N_  2048
#define C_  1024
#define H_  16
#define D_  64
#define M_  (B_*N_)   // 16384
#define LN10000 9.210340371976184f
#define NKPART 8

// ---------------- device scratch (allocation-free contract) ----------------
__device__ float g_q[M_*C_];                 // gelu(q)+0.21, PRE-rope
__device__ float g_k[M_*C_];                 // gelu(k)+0.21, PRE-rope
__device__ float g_v[M_*C_];
__device__ float g_attn[M_*C_];
__device__ float g_ksum[B_*C_];
__device__ float g_kv[B_*H_*D_*D_];
__device__ float g_kvp[NKPART][B_*H_*D_*D_];
__device__ float g_ksump[NKPART][B_*C_];
__device__ float2 g_tab[N_*(C_/2)];          // rope (cos,sin) per (n, pair)
__device__ __half g_xhi[M_*C_];
__device__ __half g_xlo[M_*C_];
__device__ __half g_whi[3][C_*C_];

__device__ __forceinline__ float gelu_exact(float x){
    return 0.5f*x*(1.0f+erff(x*0.70710678118654752f));
}
__device__ __forceinline__ uint32_t smem_u32(const void* p){
    uint32_t a;
    asm("{ .reg .u64 t; cvta.to.shared.u64 t, %1; cvt.u32.u64 %0, t; }" : "=r"(a) : "l"(p));
    return a;
}
__device__ __forceinline__ void ldm4(uint32_t* r, uint32_t addr){
    asm volatile("ldmatrix.sync.aligned.m8n8.x4.shared.b16 {%0,%1,%2,%3}, [%4];"
        : "=r"(r[0]),"=r"(r[1]),"=r"(r[2]),"=r"(r[3]) : "r"(addr));
}
__device__ __forceinline__ void mma16816(float* c, const uint32_t* a, const uint32_t* b){
    asm volatile("mma.sync.aligned.m16n8k16.row.col.f32.f16.f16.f32 "
        "{%0,%1,%2,%3}, {%4,%5,%6,%7}, {%8,%9}, {%0,%1,%2,%3};"
        : "+f"(c[0]), "+f"(c[1]), "+f"(c[2]), "+f"(c[3])
        : "r"(a[0]), "r"(a[1]), "r"(a[2]), "r"(a[3]), "r"(b[0]), "r"(b[1]));
}

// ---------------- rope table ----------------
__global__ void rope_table_kernel(){
    int idx = blockIdx.x*256 + threadIdx.x;      // n*512 + p
    int n = idx >> 9;
    int p = idx & 511;
    float invf = expf(-((float)(2*p) / 1024.f) * LN10000);
    float s, c;
    sincosf((float)n * invf, &s, &c);
    g_tab[idx] = make_float2(c, s);
}

// ---------------- fp32 -> fp16 hi/lo split (x) and fp16 (W) ----------------
__global__ void conv_x_kernel(const float* __restrict__ X){
    size_t i = ((size_t)blockIdx.x*256 + threadIdx.x)*4;
    float4 v = *(const float4*)(X + i);
    __half h0 = __float2half(v.x), h1 = __float2half(v.y);
    __half h2 = __float2half(v.z), h3 = __float2half(v.w);
    __half l0 = __float2half(v.x - __half2float(h0));
    __half l1 = __float2half(v.y - __half2float(h1));
    __half l2 = __float2half(v.z - __half2float(h2));
    __half l3 = __float2half(v.w - __half2float(h3));
    __half2 ha = __halves2half2(h0,h1), hb = __halves2half2(h2,h3);
    __half2 la = __halves2half2(l0,l1), lb = __halves2half2(l2,l3);
    uint2 hu, lu;
    hu.x = *(uint32_t*)&ha; hu.y = *(uint32_t*)&hb;
    lu.x = *(uint32_t*)&la; lu.y = *(uint32_t*)&lb;
    *(uint2*)(g_xhi + i) = hu;
    *(uint2*)(g_xlo + i) = lu;
}

__global__ void conv_w_kernel(const float* __restrict__ Wq,
                              const float* __restrict__ Wk,
                              const float* __restrict__ Wv){
    const int w = blockIdx.y;
    const float* W = (w==0)? Wq : (w==1)? Wk : Wv;
    size_t i = ((size_t)blockIdx.x*256 + threadIdx.x)*4;
    float4 v = *(const float4*)(W + i);
    __half2 ha = __halves2half2(__float2half(v.x), __float2half(v.y));
    __half2 hb = __halves2half2(__float2half(v.z), __float2half(v.w));
    uint2 hu;
    hu.x = *(uint32_t*)&ha; hu.y = *(uint32_t*)&hb;
    *(uint2*)(g_whi[w] + i) = hu;
}

// ---------------------------------------------------------------------------
// mma.sync fp16 GEMM, concat-K = [xhi|xlo] . [Whi|Whi]  (= x . fp16(W))
// Tiles: 128x128x64, 3-stage cp.async (prefetch distance 2),
// 8 warps (4m x 2n), warp tile 32x64. 2 CTAs/SM.
// ---------------------------------------------------------------------------
#define BM 128
#define BN 128
#define BK 64
#define ASTRIDE 144                     // 128B row + 16B pad (conflict-free ldmatrix)
#define TILE_BYTES (BM*ASTRIDE)         // 18432
#define STAGE_BYTES (2*TILE_BYTES)      // 36864
#define SMEM_TOT (3*STAGE_BYTES)        // 110592
#define NCHUNK 32

__device__ __forceinline__ void stage_load(uint32_t sa, uint32_t sbB, int chunk,
                                           int w, int m0, int n0, int tid){
    const int pass = chunk >> 4;        // 0: xhi, 1: xlo
    const int kk = (chunk & 15) << 6;   // fp16 element offset in [0,1024)
    const __half* Asrc = pass ? g_xlo : g_xhi;
    const __half* Bsrc = g_whi[w];
    #pragma unroll
    for (int r = 0; r < 4; r++){
        int cid = tid + r*256;          // 0..1023
        int row = cid >> 3, ch = cid & 7;
        uint64_t ga = (uint64_t)__cvta_generic_to_global(
            (const void*)(Asrc + (size_t)(m0+row)*C_ + kk + ch*8));
        asm volatile("cp.async.cg.shared.global [%0], [%1], 16;"
                     :: "r"(sa + row*ASTRIDE + ch*16), "l"(ga));
        uint64_t gb = (uint64_t)__cvta_generic_to_global(
            (const void*)(Bsrc + (size_t)(n0+row)*C_ + kk + ch*8));
        asm volatile("cp.async.cg.shared.global [%0], [%1], 16;"
                     :: "r"(sbB + row*ASTRIDE + ch*16), "l"(gb));
    }
}

__global__ void __launch_bounds__(256,2) mma_gemm_kernel(
    const float* __restrict__ bq, const float* __restrict__ bk, const float* __restrict__ bv)
{
    extern __shared__ char smem[];
    const int tid  = threadIdx.x;
    const int lane = tid & 31;
    const int wid  = tid >> 5;
    const int wm   = wid & 3;       // m offset *32
    const int wn   = wid >> 2;      // n offset *64
    const int w  = blockIdx.z;
    const int n0 = blockIdx.x * BN;
    const int m0 = blockIdx.y * BM;
    const uint32_t sb = smem_u32(smem);

    float acc[2][8][4];
    #pragma unroll
    for (int a = 0; a < 2; a++)
        #pragma unroll
        for (int bb = 0; bb < 8; bb++)
            #pragma unroll
            for (int cdx = 0; cdx < 4; cdx++) acc[a][bb][cdx] = 0.f;

    // prologue: stages 0,1
    #pragma unroll
    for (int s = 0; s < 2; s++){
        stage_load(sb + s*STAGE_BYTES, sb + s*STAGE_BYTES + TILE_BYTES, s, w, m0, n0, tid);
        asm volatile("cp.async.commit_group;" ::: "memory");
    }

    const uint32_t a_off = (uint32_t)((wm*32 + (lane & 15))*ASTRIDE + ((lane >> 4) << 3)*2);
    const uint32_t b_off = (uint32_t)((wn*64 + (lane & 7) + ((lane >> 4) << 3))*ASTRIDE
                                      + (((lane >> 3) & 1) << 3)*2);

    int bufc = 0;   // buffer of stage i
    for (int i = 0; i < NCHUNK; i++){
        if (i < NCHUNK-1) asm volatile("cp.async.wait_group 1;" ::: "memory");
        else              asm volatile("cp.async.wait_group 0;" ::: "memory");
        __syncthreads();

        if (i + 2 < NCHUNK){
            int bn = bufc + 2; if (bn >= 3) bn -= 3;
            stage_load(sb + bn*STAGE_BYTES, sb + bn*STAGE_BYTES + TILE_BYTES,
                       i+2, w, m0, n0, tid);
            asm volatile("cp.async.commit_group;" ::: "memory");
        }

        const uint32_t abase = sb + bufc*STAGE_BYTES;
        const uint32_t bbase = abase + TILE_BYTES;
        #pragma unroll
        for (int ks = 0; ks < 4; ks++){
            uint32_t af[2][4];
            #pragma unroll
            for (int fm = 0; fm < 2; fm++)
                ldm4(af[fm], abase + a_off + fm*16*ASTRIDE + ks*32);
            #pragma unroll
            for (int fn2 = 0; fn2 < 4; fn2++){
                uint32_t bf[4];
                ldm4(bf, bbase + b_off + fn2*16*ASTRIDE + ks*32);
                #pragma unroll
                for (int fm = 0; fm < 2; fm++){
                    mma16816(acc[fm][fn2*2],   af[fm], bf);
                    mma16816(acc[fm][fn2*2+1], af[fm], bf+2);
                }
            }
        }
        if (++bufc == 3) bufc = 0;
    }

    // epilogue: bias + (gelu+0.21 for q,k)
    const float* bias = (w==0)? bq : (w==1)? bk : bv;
    float* OUT = (w==0)? g_q : (w==1)? g_k : g_v;
    #pragma unroll
    for (int fm = 0; fm < 2; fm++){
        const int row0 = m0 + wm*32 + fm*16 + (lane >> 2);
        #pragma unroll
        for (int fn = 0; fn < 8; fn++){
            const int col = n0 + wn*64 + fn*8 + (lane & 3)*2;
            const float b0 = bias[col], b1 = bias[col+1];
            float v0 = acc[fm][fn][0] + b0;
            float v1 = acc[fm][fn][1] + b1;
            float v2 = acc[fm][fn][2] + b0;
            float v3 = acc[fm][fn][3] + b1;
            if (w < 2){
                v0 = gelu_exact(v0) + 0.21f;
                v1 = gelu_exact(v1) + 0.21f;
                v2 = gelu_exact(v2) + 0.21f;
                v3 = gelu_exact(v3) + 0.21f;
            }
            float2 o01; o01.x = v0; o01.y = v1;
            float2 o23; o23.x = v2; o23.y = v3;
            *(float2*)(OUT + (size_t)row0*C_ + col)     = o01;
            *(float2*)(OUT + (size_t)(row0+8)*C_ + col) = o23;
        }
    }
}

// ---------------------------------------------------------------------------
// kv partials: part p covers rows [p*256, p*256+256).
// ---------------------------------------------------------------------------
__global__ __launch_bounds__(256,1) void kv_part_kernel()
{
    const int bh = blockIdx.x;
    const int part = blockIdx.y;
    const int b = bh >> 4, h = bh & 15;
    __shared__ float ks[64][68];
    __shared__ float vs[64][68];
    __shared__ float cs[16][68];

    const int tid = threadIdx.x;
    const int te = tid & 15, td = tid >> 4;
    const int c4 = tid & 15;
    const int p0 = (h*D_ + c4*4) >> 1;

    float acc[4][4];
    #pragma unroll
    for (int i = 0; i < 4; i++)
        #pragma unroll
        for (int j = 0; j < 4; j++) acc[i][j] = 0.f;
    float csum[4] = {0.f,0.f,0.f,0.f};

    const float* kbase = g_k + (size_t)b*N_*C_ + h*D_;
    const float* vbase = g_v + (size_t)b*N_*C_ + h*D_;
    const int nstart = part * (N_/NKPART);

    for (int nt = nstart; nt < nstart + N_/NKPART; nt += 64) {
        #pragma unroll
        for (int l = 0; l < 4; l++) {
            int row = (tid >> 4) + l*16;
            int n = nt + row;
            float4 kk = *(const float4*)(kbase + (size_t)n*C_ + c4*4);
            csum[0] += kk.x; csum[1] += kk.y; csum[2] += kk.z; csum[3] += kk.w;
            float2 t0 = g_tab[n*(C_/2) + p0];
            float2 t1 = g_tab[n*(C_/2) + p0 + 1];
            float4 r;
            r.x = kk.x*t0.x - kk.y*t0.y;
            r.y = kk.y*t0.x + kk.x*t0.y;
            r.z = kk.z*t1.x - kk.w*t1.y;
            r.w = kk.w*t1.x + kk.z*t1.y;
            *(float4*)&ks[row][c4*4] = r;
            *(float4*)&vs[row][c4*4] = *(const float4*)(vbase + (size_t)n*C_ + c4*4);
        }
        __syncthreads();
        #pragma unroll 8
        for (int nn = 0; nn < 64; nn++) {
            float4 kd = *(const float4*)&ks[nn][td*4];
            float4 ve = *(const float4*)&vs[nn][te*4];
            float kv4[4] = {kd.x, kd.y, kd.z, kd.w};
            float vv4[4] = {ve.x, ve.y, ve.z, ve.w};
            #pragma unroll
            for (int i = 0; i < 4; i++)
                #pragma unroll
                for (int j = 0; j < 4; j++)
                    acc[i][j] = fmaf(kv4[i], vv4[j], acc[i][j]);
        }
        __syncthreads();
    }

    *(float4*)&cs[tid>>4][c4*4] = make_float4(csum[0], csum[1], csum[2], csum[3]);
    __syncthreads();
    if (tid < 64) {
        float s = 0.f;
        #pragma unroll
        for (int r2 = 0; r2 < 16; r2++) s += cs[r2][tid];
        g_ksump[part][b*C_ + h*D_ + tid] = s;
    }

    float* kvout = g_kvp[part] + ((size_t)bh*D_ + td*4)*D_ + te*4;
    #pragma unroll
    for (int i = 0; i < 4; i++) {
        float4 o;
        o.x = acc[i][0]; o.y = acc[i][1]; o.z = acc[i][2]; o.w = acc[i][3];
        *(float4*)(kvout + i*D_) = o;
    }
}

__global__ __launch_bounds__(256,1) void kv_reduce_kernel()
{
    const int idx = blockIdx.x*256 + threadIdx.x;   // 0 .. B*H*D*D-1
    float s = 0.f;
    #pragma unroll
    for (int p = 0; p < NKPART; p++) s += g_kvp[p][idx];
    g_kv[idx] = s * (1.f / (float)N_);
    if (idx < B_*C_) {
        float t = 0.f;
        #pragma unroll
        for (int p = 0; p < NKPART; p++) t += g_ksump[p][idx];
        g_ksum[idx] = t;
    }
}

// ---------------------------------------------------------------------------
// out_attn = z * (rope(q) @ kv); z = 1/(dot(q_pre, kmean)+1e-6). Table rope.
// ---------------------------------------------------------------------------
__global__ __launch_bounds__(256,1) void zout_kernel()
{
    const int bh = blockIdx.y;
    const int b = bh >> 4, h = bh & 15;
    const int n0 = blockIdx.x * 64;

    __shared__ float qs[64][68];
    __shared__ float kvs[64][68];
    __shared__ float kms[64];
    __shared__ float zsh[64];

    const int tid = threadIdx.x;
    const int row = tid >> 2;
    const int qtr = tid & 3;

    if (tid < 64) kms[tid] = g_ksum[b*C_ + h*D_ + tid] * (1.f / (float)N_);
    __syncthreads();

    const int n = n0 + row;
    const float* qrow = g_q + ((size_t)(b*N_ + n))*C_ + h*D_;
    const int pbase = (h*D_ + qtr*16) >> 1;
    float zp = 0.f;
    #pragma unroll
    for (int l = 0; l < 4; l++) {
        int cl = qtr*16 + l*4;
        float4 qv = *(const float4*)(qrow + cl);
        zp += qv.x*kms[cl] + qv.y*kms[cl+1] + qv.z*kms[cl+2] + qv.w*kms[cl+3];
        float2 t0 = g_tab[n*(C_/2) + pbase + l*2];
        float2 t1 = g_tab[n*(C_/2) + pbase + l*2 + 1];
        float4 r;
        r.x = qv.x*t0.x - qv.y*t0.y;
        r.y = qv.y*t0.x + qv.x*t0.y;
        r.z = qv.z*t1.x - qv.w*t1.y;
        r.w = qv.w*t1.x + qv.z*t1.y;
        *(float4*)&qs[row][cl] = r;
    }
    #pragma unroll
    for (int l = 0; l < 4; l++) {
        int idx = tid + l*256;
        int rd = idx >> 4;
        int cc4 = idx & 15;
        *(float4*)&kvs[rd][cc4*4] = *(const float4*)(g_kv + (size_t)bh*D_*D_ + rd*D_ + cc4*4);
    }
    zp += __shfl_xor_sync(0xffffffffu, zp, 1);
    zp += __shfl_xor_sync(0xffffffffu, zp, 2);
    if (qtr == 0) zsh[row] = 1.f / (zp + 1e-6f);
    __syncthreads();

    float acc[16];
    #pragma unroll
    for (int e = 0; e < 16; e++) acc[e] = 0.f;
    #pragma unroll 8
    for (int d = 0; d < 64; d++) {
        float qv = qs[row][d];
        #pragma unroll
        for (int l = 0; l < 4; l++) {
            float4 k4 = *(const float4*)&kvs[d][qtr*16 + l*4];
            acc[l*4+0] = fmaf(qv, k4.x, acc[l*4+0]);
            acc[l*4+1] = fmaf(qv, k4.y, acc[l*4+1]);
            acc[l*4+2] = fmaf(qv, k4.z, acc[l*4+2]);
            acc[l*4+3] = fmaf(qv, k4.w, acc[l*4+3]);
        }
    }
    const float z = zsh[row];
    float* o = g_attn + ((size_t)(b*N_ + n))*C_ + h*D_ + qtr*16;
    #pragma unroll
    for (int l = 0; l < 4; l++) {
        float4 r;
        r.x = acc[l*4+0]*z; r.y = acc[l*4+1]*z; r.z = acc[l*4+2]*z; r.w = acc[l*4+3]*z;
        *(float4*)(o + l*4) = r;
    }
}

// ---------------------------------------------------------------------------
// residual + LayerNorm
// ---------------------------------------------------------------------------
__global__ __launch_bounds__(256,1) void ln_kernel(
    const float* __restrict__ X,
    const float* __restrict__ gamma,
    const float* __restrict__ beta,
    float* __restrict__ out)
{
    const int m = blockIdx.x;
    const int tid = threadIdx.x;
    const float* xr = X + (size_t)m*C_;
    const float* ar = g_attn + (size_t)m*C_;

    float4 xv = *(const float4*)(xr + tid*4);
    float4 av = *(const float4*)(ar + tid*4);
    float4 r;
    r.x = xv.x + av.x; r.y = xv.y + av.y; r.z = xv.z + av.z; r.w = xv.w + av.w;

    float s1 = r.x + r.y + r.z + r.w;
    float s2 = r.x*r.x + r.y*r.y + r.z*r.z + r.w*r.w;
    #pragma unroll
    for (int o = 16; o > 0; o >>= 1) {
        s1 += __shfl_xor_sync(0xffffffffu, s1, o);
        s2 += __shfl_xor_sync(0xffffffffu, s2, o);
    }
    __shared__ float rs1[8], rs2[8], stats[2];
    int wid = tid >> 5, lane = tid & 31;
    if (lane == 0) { rs1[wid] = s1; rs2[wid] = s2; }
    __syncthreads();
    if (tid == 0) {
        float a = 0.f, bsum = 0.f;
        #pragma unroll
        for (int i = 0; i < 8; i++) { a += rs1[i]; bsum += rs2[i]; }
        stats[0] = a; stats[1] = bsum;
    }
    __syncthreads();
    float mean = stats[0] * (1.f / (float)C_);
    float var  = stats[1] * (1.f / (float)C_) - mean*mean;
    float inv  = rsqrtf(var + 1e-12f);

    float4 g4 = *(const float4*)(gamma + tid*4);
    float4 b4 = *(const float4*)(beta + tid*4);
    float4 o;
    o.x = (r.x - mean)*inv*g4.x + b4.x;
    o.y = (r.y - mean)*inv*g4.y + b4.y;
    o.z = (r.z - mean)*inv*g4.z + b4.z;
    o.w = (r.w - mean)*inv*g4.w + b4.w;
    *(float4*)(out + (size_t)m*C_ + tid*4) = o;
}

extern "C" void kernel_launch(void* const* d_in, const int* in_sizes, int n_in,
                              void* d_out, int out_size)
{
    const float* x     = (const float*)d_in[0];
    const float* Wq    = (const float*)d_in[1];
    const float* bq    = (const float*)d_in[2];
    const float* Wk    = (const float*)d_in[3];
    const float* bk    = (const float*)d_in[4];
    const float* Wv    = (const float*)d_in[5];
    const float* bv    = (const float*)d_in[6];
    const float* gamma = (const float*)d_in[7];
    const float* beta  = (const float*)d_in[8];
    float* out = (float*)d_out;

    cudaFuncSetAttribute(mma_gemm_kernel, cudaFuncAttributeMaxDynamicSharedMemorySize, SMEM_TOT);

    rope_table_kernel<<<(N_*(C_/2))/256, 256>>>();
    conv_x_kernel<<<(M_*C_)/1024, 256>>>(x);
    conv_w_kernel<<<dim3((C_*C_)/1024, 3), 256>>>(Wq, Wk, Wv);
    mma_gemm_kernel<<<dim3(C_/BN, M_/BM, 3), 256, SMEM_TOT>>>(bq, bk, bv);
    kv_part_kernel<<<dim3(B_*H_, NKPART), 256>>>();
    kv_reduce_kernel<<<(B_*H_*D_*D_)/256, 256>>>();
    zout_kernel<<<dim3(N_/64, B_*H_), 256>>>();
    ln_kernel<<<M_, 256>>>(x, gamma, beta, out);
}

// round 15
// speedup vs baseline: 1.9089x; 1.3775x over previous
#include <cuda_runtime.h>
#include <cuda_fp16.h>
#include <math.h>
#include <stdint.h>

#define B_  8
#define N_  2048
#define C_  1024
#define H_  16
#define D_  64
#define M_  (B_*N_)   // 16384
#define LN10000 9.210340371976184f
#define NKPART 8

// ---------------- device scratch (allocation-free contract) ----------------
__device__ float g_q[M_*C_];                 // gelu(q)+0.21, PRE-rope
__device__ float g_k[M_*C_];                 // gelu(k)+0.21, PRE-rope
__device__ float g_v[M_*C_];
__device__ float g_attn[M_*C_];
__device__ float g_ksum[B_*C_];
__device__ float g_kv[B_*H_*D_*D_];
__device__ float g_kvp[NKPART][B_*H_*D_*D_];
__device__ float g_ksump[NKPART][B_*C_];
__device__ float2 g_tab[N_*(C_/2)];          // rope (cos,sin) per (n, pair)
__device__ __half g_xh[M_*C_];
__device__ __half g_wh[3][C_*C_];

__device__ __forceinline__ float gelu_exact(float x){
    return 0.5f*x*(1.0f+erff(x*0.70710678118654752f));
}
__device__ __forceinline__ uint32_t smem_u32(const void* p){
    uint32_t a;
    asm("{ .reg .u64 t; cvta.to.shared.u64 t, %1; cvt.u32.u64 %0, t; }" : "=r"(a) : "l"(p));
    return a;
}
__device__ __forceinline__ void ldm4(uint32_t* r, uint32_t addr){
    asm volatile("ldmatrix.sync.aligned.m8n8.x4.shared.b16 {%0,%1,%2,%3}, [%4];"
        : "=r"(r[0]),"=r"(r[1]),"=r"(r[2]),"=r"(r[3]) : "r"(addr));
}
__device__ __forceinline__ void mma16816(float* c, const uint32_t* a, const uint32_t* b){
    asm volatile("mma.sync.aligned.m16n8k16.row.col.f32.f16.f16.f32 "
        "{%0,%1,%2,%3}, {%4,%5,%6,%7}, {%8,%9}, {%0,%1,%2,%3};"
        : "+f"(c[0]), "+f"(c[1]), "+f"(c[2]), "+f"(c[3])
        : "r"(a[0]), "r"(a[1]), "r"(a[2]), "r"(a[3]), "r"(b[0]), "r"(b[1]));
}

// ---------------- rope table ----------------
__global__ void rope_table_kernel(){
    int idx = blockIdx.x*256 + threadIdx.x;      // n*512 + p
    int n = idx >> 9;
    int p = idx & 511;
    float invf = expf(-((float)(2*p) / 1024.f) * LN10000);
    float s, c;
    sincosf((float)n * invf, &s, &c);
    g_tab[idx] = make_float2(c, s);
}

// ---------------- fp32 -> fp16 casts ----------------
__global__ void conv_x_kernel(const float* __restrict__ X){
    size_t i = ((size_t)blockIdx.x*256 + threadIdx.x)*4;
    float4 v = *(const float4*)(X + i);
    __half2 ha = __halves2half2(__float2half(v.x), __float2half(v.y));
    __half2 hb = __halves2half2(__float2half(v.z), __float2half(v.w));
    uint2 hu;
    hu.x = *(uint32_t*)&ha; hu.y = *(uint32_t*)&hb;
    *(uint2*)(g_xh + i) = hu;
}

__global__ void conv_w_kernel(const float* __restrict__ Wq,
                              const float* __restrict__ Wk,
                              const float* __restrict__ Wv){
    const int w = blockIdx.y;
    const float* W = (w==0)? Wq : (w==1)? Wk : Wv;
    size_t i = ((size_t)blockIdx.x*256 + threadIdx.x)*4;
    float4 v = *(const float4*)(W + i);
    __half2 ha = __halves2half2(__float2half(v.x), __float2half(v.y));
    __half2 hb = __halves2half2(__float2half(v.z), __float2half(v.w));
    uint2 hu;
    hu.x = *(uint32_t*)&ha; hu.y = *(uint32_t*)&hb;
    *(uint2*)(g_wh[w] + i) = hu;
}

// ---------------------------------------------------------------------------
// mma.sync fp16 GEMM: fp16(x) . fp16(W), K=1024.
// Tiles: 128x128x64, 3-stage cp.async (prefetch distance 2),
// 8 warps (4m x 2n), warp tile 32x64. 2 CTAs/SM.
// ---------------------------------------------------------------------------
#define BM 128
#define BN 128
#define BK 64
#define ASTRIDE 144                     // 128B row + 16B pad (conflict-free ldmatrix)
#define TILE_BYTES (BM*ASTRIDE)         // 18432
#define STAGE_BYTES (2*TILE_BYTES)      // 36864
#define SMEM_TOT (3*STAGE_BYTES)        // 110592
#define NCHUNK 16

__device__ __forceinline__ void stage_load(uint32_t sa, uint32_t sbB, int chunk,
                                           int w, int m0, int n0, int tid){
    const int kk = chunk << 6;          // fp16 element offset in [0,1024)
    const __half* Asrc = g_xh;
    const __half* Bsrc = g_wh[w];
    #pragma unroll
    for (int r = 0; r < 4; r++){
        int cid = tid + r*256;          // 0..1023
        int row = cid >> 3, ch = cid & 7;
        uint64_t ga = (uint64_t)__cvta_generic_to_global(
            (const void*)(Asrc + (size_t)(m0+row)*C_ + kk + ch*8));
        asm volatile("cp.async.cg.shared.global [%0], [%1], 16;"
                     :: "r"(sa + row*ASTRIDE + ch*16), "l"(ga));
        uint64_t gb = (uint64_t)__cvta_generic_to_global(
            (const void*)(Bsrc + (size_t)(n0+row)*C_ + kk + ch*8));
        asm volatile("cp.async.cg.shared.global [%0], [%1], 16;"
                     :: "r"(sbB + row*ASTRIDE + ch*16), "l"(gb));
    }
}

__global__ void __launch_bounds__(256,2) mma_gemm_kernel(
    const float* __restrict__ bq, const float* __restrict__ bk, const float* __restrict__ bv)
{
    extern __shared__ char smem[];
    const int tid  = threadIdx.x;
    const int lane = tid & 31;
    const int wid  = tid >> 5;
    const int wm   = wid & 3;       // m offset *32
    const int wn   = wid >> 2;      // n offset *64
    const int w  = blockIdx.z;
    const int n0 = blockIdx.x * BN;
    const int m0 = blockIdx.y * BM;
    const uint32_t sb = smem_u32(smem);

    float acc[2][8][4];
    #pragma unroll
    for (int a = 0; a < 2; a++)
        #pragma unroll
        for (int bb = 0; bb < 8; bb++)
            #pragma unroll
            for (int cdx = 0; cdx < 4; cdx++) acc[a][bb][cdx] = 0.f;

    // prologue: stages 0,1
    #pragma unroll
    for (int s = 0; s < 2; s++){
        stage_load(sb + s*STAGE_BYTES, sb + s*STAGE_BYTES + TILE_BYTES, s, w, m0, n0, tid);
        asm volatile("cp.async.commit_group;" ::: "memory");
    }

    const uint32_t a_off = (uint32_t)((wm*32 + (lane & 15))*ASTRIDE + ((lane >> 4) << 3)*2);
    const uint32_t b_off = (uint32_t)((wn*64 + (lane & 7) + ((lane >> 4) << 3))*ASTRIDE
                                      + (((lane >> 3) & 1) << 3)*2);

    int bufc = 0;   // buffer of stage i
    for (int i = 0; i < NCHUNK; i++){
        if (i < NCHUNK-1) asm volatile("cp.async.wait_group 1;" ::: "memory");
        else              asm volatile("cp.async.wait_group 0;" ::: "memory");
        __syncthreads();

        if (i + 2 < NCHUNK){
            int bn = bufc + 2; if (bn >= 3) bn -= 3;
            stage_load(sb + bn*STAGE_BYTES, sb + bn*STAGE_BYTES + TILE_BYTES,
                       i+2, w, m0, n0, tid);
            asm volatile("cp.async.commit_group;" ::: "memory");
        }

        const uint32_t abase = sb + bufc*STAGE_BYTES;
        const uint32_t bbase = abase + TILE_BYTES;
        #pragma unroll
        for (int ks = 0; ks < 4; ks++){
            uint32_t af[2][4];
            #pragma unroll
            for (int fm = 0; fm < 2; fm++)
                ldm4(af[fm], abase + a_off + fm*16*ASTRIDE + ks*32);
            #pragma unroll
            for (int fn2 = 0; fn2 < 4; fn2++){
                uint32_t bf[4];
                ldm4(bf, bbase + b_off + fn2*16*ASTRIDE + ks*32);
                #pragma unroll
                for (int fm = 0; fm < 2; fm++){
                    mma16816(acc[fm][fn2*2],   af[fm], bf);
                    mma16816(acc[fm][fn2*2+1], af[fm], bf+2);
                }
            }
        }
        if (++bufc == 3) bufc = 0;
    }

    // epilogue: bias + (gelu+0.21 for q,k)
    const float* bias = (w==0)? bq : (w==1)? bk : bv;
    float* OUT = (w==0)? g_q : (w==1)? g_k : g_v;
    #pragma unroll
    for (int fm = 0; fm < 2; fm++){
        const int row0 = m0 + wm*32 + fm*16 + (lane >> 2);
        #pragma unroll
        for (int fn = 0; fn < 8; fn++){
            const int col = n0 + wn*64 + fn*8 + (lane & 3)*2;
            const float b0 = bias[col], b1 = bias[col+1];
            float v0 = acc[fm][fn][0] + b0;
            float v1 = acc[fm][fn][1] + b1;
            float v2 = acc[fm][fn][2] + b0;
            float v3 = acc[fm][fn][3] + b1;
            if (w < 2){
                v0 = gelu_exact(v0) + 0.21f;
                v1 = gelu_exact(v1) + 0.21f;
                v2 = gelu_exact(v2) + 0.21f;
                v3 = gelu_exact(v3) + 0.21f;
            }
            float2 o01; o01.x = v0; o01.y = v1;
            float2 o23; o23.x = v2; o23.y = v3;
            *(float2*)(OUT + (size_t)row0*C_ + col)     = o01;
            *(float2*)(OUT + (size_t)(row0+8)*C_ + col) = o23;
        }
    }
}

// ---------------------------------------------------------------------------
// kv partials: part p covers rows [p*256, p*256+256).
// ---------------------------------------------------------------------------
__global__ __launch_bounds__(256,1) void kv_part_kernel()
{
    const int bh = blockIdx.x;
    const int part = blockIdx.y;
    const int b = bh >> 4, h = bh & 15;
    __shared__ float ks[64][68];
    __shared__ float vs[64][68];
    __shared__ float cs[16][68];

    const int tid = threadIdx.x;
    const int te = tid & 15, td = tid >> 4;
    const int c4 = tid & 15;
    const int p0 = (h*D_ + c4*4) >> 1;

    float acc[4][4];
    #pragma unroll
    for (int i = 0; i < 4; i++)
        #pragma unroll
        for (int j = 0; j < 4; j++) acc[i][j] = 0.f;
    float csum[4] = {0.f,0.f,0.f,0.f};

    const float* kbase = g_k + (size_t)b*N_*C_ + h*D_;
    const float* vbase = g_v + (size_t)b*N_*C_ + h*D_;
    const int nstart = part * (N_/NKPART);

    for (int nt = nstart; nt < nstart + N_/NKPART; nt += 64) {
        #pragma unroll
        for (int l = 0; l < 4; l++) {
            int row = (tid >> 4) + l*16;
            int n = nt + row;
            float4 kk = *(const float4*)(kbase + (size_t)n*C_ + c4*4);
            csum[0] += kk.x; csum[1] += kk.y; csum[2] += kk.z; csum[3] += kk.w;
            float2 t0 = g_tab[n*(C_/2) + p0];
            float2 t1 = g_tab[n*(C_/2) + p0 + 1];
            float4 r;
            r.x = kk.x*t0.x - kk.y*t0.y;
            r.y = kk.y*t0.x + kk.x*t0.y;
            r.z = kk.z*t1.x - kk.w*t1.y;
            r.w = kk.w*t1.x + kk.z*t1.y;
            *(float4*)&ks[row][c4*4] = r;
            *(float4*)&vs[row][c4*4] = *(const float4*)(vbase + (size_t)n*C_ + c4*4);
        }
        __syncthreads();
        #pragma unroll 8
        for (int nn = 0; nn < 64; nn++) {
            float4 kd = *(const float4*)&ks[nn][td*4];
            float4 ve = *(const float4*)&vs[nn][te*4];
            float kv4[4] = {kd.x, kd.y, kd.z, kd.w};
            float vv4[4] = {ve.x, ve.y, ve.z, ve.w};
            #pragma unroll
            for (int i = 0; i < 4; i++)
                #pragma unroll
                for (int j = 0; j < 4; j++)
                    acc[i][j] = fmaf(kv4[i], vv4[j], acc[i][j]);
        }
        __syncthreads();
    }

    *(float4*)&cs[tid>>4][c4*4] = make_float4(csum[0], csum[1], csum[2], csum[3]);
    __syncthreads();
    if (tid < 64) {
        float s = 0.f;
        #pragma unroll
        for (int r2 = 0; r2 < 16; r2++) s += cs[r2][tid];
        g_ksump[part][b*C_ + h*D_ + tid] = s;
    }

    float* kvout = g_kvp[part] + ((size_t)bh*D_ + td*4)*D_ + te*4;
    #pragma unroll
    for (int i = 0; i < 4; i++) {
        float4 o;
        o.x = acc[i][0]; o.y = acc[i][1]; o.z = acc[i][2]; o.w = acc[i][3];
        *(float4*)(kvout + i*D_) = o;
    }
}

__global__ __launch_bounds__(256,1) void kv_reduce_kernel()
{
    const int idx = blockIdx.x*256 + threadIdx.x;   // 0 .. B*H*D*D-1
    float s = 0.f;
    #pragma unroll
    for (int p = 0; p < NKPART; p++) s += g_kvp[p][idx];
    g_kv[idx] = s * (1.f / (float)N_);
    if (idx < B_*C_) {
        float t = 0.f;
        #pragma unroll
        for (int p = 0; p < NKPART; p++) t += g_ksump[p][idx];
        g_ksum[idx] = t;
    }
}

// ---------------------------------------------------------------------------
// out_attn = z * (rope(q) @ kv); z = 1/(dot(q_pre, kmean)+1e-6). Table rope.
// ---------------------------------------------------------------------------
__global__ __launch_bounds__(256,1) void zout_kernel()
{
    const int bh = blockIdx.y;
    const int b = bh >> 4, h = bh & 15;
    const int n0 = blockIdx.x * 64;

    __shared__ float qs[64][68];
    __shared__ float kvs[64][68];
    __shared__ float kms[64];
    __shared__ float zsh[64];

    const int tid = threadIdx.x;
    const int row = tid >> 2;
    const int qtr = tid & 3;

    if (tid < 64) kms[tid] = g_ksum[b*C_ + h*D_ + tid] * (1.f / (float)N_);
    __syncthreads();

    const int n = n0 + row;
    const float* qrow = g_q + ((size_t)(b*N_ + n))*C_ + h*D_;
    const int pbase = (h*D_ + qtr*16) >> 1;
    float zp = 0.f;
    #pragma unroll
    for (int l = 0; l < 4; l++) {
        int cl = qtr*16 + l*4;
        float4 qv = *(const float4*)(qrow + cl);
        zp += qv.x*kms[cl] + qv.y*kms[cl+1] + qv.z*kms[cl+2] + qv.w*kms[cl+3];
        float2 t0 = g_tab[n*(C_/2) + pbase + l*2];
        float2 t1 = g_tab[n*(C_/2) + pbase + l*2 + 1];
        float4 r;
        r.x = qv.x*t0.x - qv.y*t0.y;
        r.y = qv.y*t0.x + qv.x*t0.y;
        r.z = qv.z*t1.x - qv.w*t1.y;
        r.w = qv.w*t1.x + qv.z*t1.y;
        *(float4*)&qs[row][cl] = r;
    }
    #pragma unroll
    for (int l = 0; l < 4; l++) {
        int idx = tid + l*256;
        int rd = idx >> 4;
        int cc4 = idx & 15;
        *(float4*)&kvs[rd][cc4*4] = *(const float4*)(g_kv + (size_t)bh*D_*D_ + rd*D_ + cc4*4);
    }
    zp += __shfl_xor_sync(0xffffffffu, zp, 1);
    zp += __shfl_xor_sync(0xffffffffu, zp, 2);
    if (qtr == 0) zsh[row] = 1.f / (zp + 1e-6f);
    __syncthreads();

    float acc[16];
    #pragma unroll
    for (int e = 0; e < 16; e++) acc[e] = 0.f;
    #pragma unroll 8
    for (int d = 0; d < 64; d++) {
        float qv = qs[row][d];
        #pragma unroll
        for (int l = 0; l < 4; l++) {
            float4 k4 = *(const float4*)&kvs[d][qtr*16 + l*4];
            acc[l*4+0] = fmaf(qv, k4.x, acc[l*4+0]);
            acc[l*4+1] = fmaf(qv, k4.y, acc[l*4+1]);
            acc[l*4+2] = fmaf(qv, k4.z, acc[l*4+2]);
            acc[l*4+3] = fmaf(qv, k4.w, acc[l*4+3]);
        }
    }
    const float z = zsh[row];
    float* o = g_attn + ((size_t)(b*N_ + n))*C_ + h*D_ + qtr*16;
    #pragma unroll
    for (int l = 0; l < 4; l++) {
        float4 r;
        r.x = acc[l*4+0]*z; r.y = acc[l*4+1]*z; r.z = acc[l*4+2]*z; r.w = acc[l*4+3]*z;
        *(float4*)(o + l*4) = r;
    }
}

// ---------------------------------------------------------------------------
// residual + LayerNorm
// ---------------------------------------------------------------------------
__global__ __launch_bounds__(256,1) void ln_kernel(
    const float* __restrict__ X,
    const float* __restrict__ gamma,
    const float* __restrict__ beta,
    float* __restrict__ out)
{
    const int m = blockIdx.x;
    const int tid = threadIdx.x;
    const float* xr = X + (size_t)m*C_;
    const float* ar = g_attn + (size_t)m*C_;

    float4 xv = *(const float4*)(xr + tid*4);
    float4 av = *(const float4*)(ar + tid*4);
    float4 r;
    r.x = xv.x + av.x; r.y = xv.y + av.y; r.z = xv.z + av.z; r.w = xv.w + av.w;

    float s1 = r.x + r.y + r.z + r.w;
    float s2 = r.x*r.x + r.y*r.y + r.z*r.z + r.w*r.w;
    #pragma unroll
    for (int o = 16; o > 0; o >>= 1) {
        s1 += __shfl_xor_sync(0xffffffffu, s1, o);
        s2 += __shfl_xor_sync(0xffffffffu, s2, o);
    }
    __shared__ float rs1[8], rs2[8], stats[2];
    int wid = tid >> 5, lane = tid & 31;
    if (lane == 0) { rs1[wid] = s1; rs2[wid] = s2; }
    __syncthreads();
    if (tid == 0) {
        float a = 0.f, bsum = 0.f;
        #pragma unroll
        for (int i = 0; i < 8; i++) { a += rs1[i]; bsum += rs2[i]; }
        stats[0] = a; stats[1] = bsum;
    }
    __syncthreads();
    float mean = stats[0] * (1.f / (float)C_);
    float var  = stats[1] * (1.f / (float)C_) - mean*mean;
    float inv  = rsqrtf(var + 1e-12f);

    float4 g4 = *(const float4*)(gamma + tid*4);
    float4 b4 = *(const float4*)(beta + tid*4);
    float4 o;
    o.x = (r.x - mean)*inv*g4.x + b4.x;
    o.y = (r.y - mean)*inv*g4.y + b4.y;
    o.z = (r.z - mean)*inv*g4.z + b4.z;
    o.w = (r.w - mean)*inv*g4.w + b4.w;
    *(float4*)(out + (size_t)m*C_ + tid*4) = o;
}

extern "C" void kernel_launch(void* const* d_in, const int* in_sizes, int n_in,
                              void* d_out, int out_size)
{
    const float* x     = (const float*)d_in[0];
    const float* Wq    = (const float*)d_in[1];
    const float* bq    = (const float*)d_in[2];
    const float* Wk    = (const float*)d_in[3];
    const float* bk    = (const float*)d_in[4];
    const float* Wv    = (const float*)d_in[5];
    const float* bv    = (const float*)d_in[6];
    const float* gamma = (const float*)d_in[7];
    const float* beta  = (const float*)d_in[8];
    float* out = (float*)d_out;

    cudaFuncSetAttribute(mma_gemm_kernel, cudaFuncAttributeMaxDynamicSharedMemorySize, SMEM_TOT);

    rope_table_kernel<<<(N_*(C_/2))/256, 256>>>();
    conv_x_kernel<<<(M_*C_)/1024, 256>>>(x);
    conv_w_kernel<<<dim3((C_*C_)/1024, 3), 256>>>(Wq, Wk, Wv);
    mma_gemm_kernel<<<dim3(C_/BN, M_/BM, 3), 256, SMEM_TOT>>>(bq, bk, bv);
    kv_part_kernel<<<dim3(B_*H_, NKPART), 256>>>();
    kv_reduce_kernel<<<(B_*H_*D_*D_)/256, 256>>>();
    zout_kernel<<<dim3(N_/64, B_*H_), 256>>>();
    ln_kernel<<<M_, 256>>>(x, gamma, beta, out);
}